// round 9
// baseline (speedup 1.0000x reference)
#include <cuda_runtime.h>

// SlidingWindow: k,v (1, 2048, 16, 64) fp32, W=64
// out = concat(k_win, v_win), each (1, 2048, 16, 64, 64) fp32 layout [t][h][w][d]
// out_k[t,h,w,d] = (w < min(t+1,W)) ? k[max(0,t+1-W)+w, h, d] : 0
//
// FINAL converged configuration. Best measured 145.9us = 7.58 TB/s effective
// (~95% of 8 TB/s HBM3e spec) on the mandatory 1.07 GB output write stream:
//  - float4 granularity, block-strided ILP=8: every LDG/STG is a fully
//    coalesced 512B contiguous warp transaction, 16 independent loads/thread
//  - fast/slow block split: 96.9% of blocks (t >= 63) skip window predication
//  - __stcs evict-first stores keep the reused 32MB k/v inputs L2-resident
// Rejected by measurement: thread-contiguous ILP (store scatter, 338us),
// TPB=512 (L1tex queue overflow, 236us), 256-bit v8.f32 (cracked by ptxas).

#define H_DIM 16
#define W_DIM 64

// per-tensor float4 count: 2048*16*64*64/4 = 33,554,432
#define N4 33554432LL

#define TPB 256
#define ILP 8
// one t-slice = 16*64*16 = 16384 float4s = 8 blocks of TPB*ILP=2048.
// blocks with blockIdx >= 63*8 = 504 cover t >= 63 -> always full window.
#define FIRST_ALL_VALID_BLOCK 504

__global__ __launch_bounds__(TPB) void sliding_window_kernel(
    const float4* __restrict__ k4,
    const float4* __restrict__ v4,
    float4* __restrict__ out4)   // [0, N4) = k_win, [N4, 2N4) = v_win
{
    const long long blk = (long long)blockIdx.x * (TPB * ILP) + threadIdx.x;

    long long src[ILP];
    float4 kk[ILP], vv[ILP];

    if (blockIdx.x >= FIRST_ALL_VALID_BLOCK) {
        // fast path: t >= 63, window always full, no predication.
#pragma unroll
        for (int j = 0; j < ILP; j++) {
            const long long i = blk + (long long)j * TPB;
            const int d4 = (int)(i & 15);
            const int w  = (int)((i >> 4) & 63);
            const int h  = (int)((i >> 10) & 15);
            const int t  = (int)(i >> 14);
            const int src_t = t + 1 - W_DIM + w;
            src[j] = (((long long)src_t * H_DIM + h) << 4) + d4;
        }
#pragma unroll
        for (int j = 0; j < ILP; j++) kk[j] = __ldg(&k4[src[j]]);
#pragma unroll
        for (int j = 0; j < ILP; j++) vv[j] = __ldg(&v4[src[j]]);
    } else {
        // slow path: t < 63, window may be partial (zero-fill; start = 0).
        const float4 z = make_float4(0.f, 0.f, 0.f, 0.f);
        bool valid[ILP];
#pragma unroll
        for (int j = 0; j < ILP; j++) {
            const long long i = blk + (long long)j * TPB;
            const int d4 = (int)(i & 15);
            const int w  = (int)((i >> 4) & 63);
            const int h  = (int)((i >> 10) & 15);
            const int t  = (int)(i >> 14);
            valid[j] = (w <= t);
            src[j] = (((long long)w * H_DIM + h) << 4) + d4;
        }
#pragma unroll
        for (int j = 0; j < ILP; j++) kk[j] = valid[j] ? __ldg(&k4[src[j]]) : z;
#pragma unroll
        for (int j = 0; j < ILP; j++) vv[j] = valid[j] ? __ldg(&v4[src[j]]) : z;
    }

#pragma unroll
    for (int j = 0; j < ILP; j++)
        __stcs(&out4[blk + (long long)j * TPB], kk[j]);       // evict-first stream
#pragma unroll
    for (int j = 0; j < ILP; j++)
        __stcs(&out4[blk + (long long)j * TPB + N4], vv[j]);
}

extern "C" void kernel_launch(void* const* d_in, const int* in_sizes, int n_in,
                              void* d_out, int out_size) {
    const float4* k4 = (const float4*)d_in[0];
    const float4* v4 = (const float4*)d_in[1];
    float4* out4 = (float4*)d_out;

    const int blocks = (int)(N4 / (TPB * ILP));  // 16384
    sliding_window_kernel<<<blocks, TPB>>>(k4, v4, out4);
}

// round 10
// speedup vs baseline: 1.0055x; 1.0055x over previous
#include <cuda_runtime.h>

// SlidingWindow: k,v (1, 2048, 16, 64) fp32, W=64
// out = concat(k_win, v_win), each (1, 2048, 16, 64, 64) fp32 layout [t][h][w][d]
// out_k[t,h,w,d] = (w < min(t+1,W)) ? k[max(0,t+1-W)+w, h, d] : 0
//
// Variant of the converged config (145.9us best): TPB 256 -> 128, keeping
// ILP=8 block-strided. Same per-thread MLP (16 loads in flight), half the
// per-CTA L1tex burst, finer CTA granularity for wave balance.

#define H_DIM 16
#define W_DIM 64

// per-tensor float4 count: 2048*16*64*64/4 = 33,554,432
#define N4 33554432LL

#define TPB 128
#define ILP 8
// per-block float4s = TPB*ILP = 1024; one t-slice = 16*64*16 = 16384 float4s
// = 16 blocks. blocks with blockIdx >= 63*16 = 1008 cover t >= 63 -> full window.
#define FIRST_ALL_VALID_BLOCK 1008

__global__ __launch_bounds__(TPB) void sliding_window_kernel(
    const float4* __restrict__ k4,
    const float4* __restrict__ v4,
    float4* __restrict__ out4)   // [0, N4) = k_win, [N4, 2N4) = v_win
{
    const long long blk = (long long)blockIdx.x * (TPB * ILP) + threadIdx.x;

    long long src[ILP];
    float4 kk[ILP], vv[ILP];

    if (blockIdx.x >= FIRST_ALL_VALID_BLOCK) {
        // fast path: t >= 63, window always full, no predication.
#pragma unroll
        for (int j = 0; j < ILP; j++) {
            const long long i = blk + (long long)j * TPB;
            const int d4 = (int)(i & 15);
            const int w  = (int)((i >> 4) & 63);
            const int h  = (int)((i >> 10) & 15);
            const int t  = (int)(i >> 14);
            const int src_t = t + 1 - W_DIM + w;
            src[j] = (((long long)src_t * H_DIM + h) << 4) + d4;
        }
#pragma unroll
        for (int j = 0; j < ILP; j++) kk[j] = __ldg(&k4[src[j]]);
#pragma unroll
        for (int j = 0; j < ILP; j++) vv[j] = __ldg(&v4[src[j]]);
    } else {
        // slow path: t < 63, window may be partial (zero-fill; start = 0).
        const float4 z = make_float4(0.f, 0.f, 0.f, 0.f);
        bool valid[ILP];
#pragma unroll
        for (int j = 0; j < ILP; j++) {
            const long long i = blk + (long long)j * TPB;
            const int d4 = (int)(i & 15);
            const int w  = (int)((i >> 4) & 63);
            const int h  = (int)((i >> 10) & 15);
            const int t  = (int)(i >> 14);
            valid[j] = (w <= t);
            src[j] = (((long long)w * H_DIM + h) << 4) + d4;
        }
#pragma unroll
        for (int j = 0; j < ILP; j++) kk[j] = valid[j] ? __ldg(&k4[src[j]]) : z;
#pragma unroll
        for (int j = 0; j < ILP; j++) vv[j] = valid[j] ? __ldg(&v4[src[j]]) : z;
    }

#pragma unroll
    for (int j = 0; j < ILP; j++)
        __stcs(&out4[blk + (long long)j * TPB], kk[j]);       // evict-first stream
#pragma unroll
    for (int j = 0; j < ILP; j++)
        __stcs(&out4[blk + (long long)j * TPB + N4], vv[j]);
}

extern "C" void kernel_launch(void* const* d_in, const int* in_sizes, int n_in,
                              void* d_out, int out_size) {
    const float4* k4 = (const float4*)d_in[0];
    const float4* v4 = (const float4*)d_in[1];
    float4* out4 = (float4*)d_out;

    const int blocks = (int)(N4 / (TPB * ILP));  // 32768
    sliding_window_kernel<<<blocks, TPB>>>(k4, v4, out4);
}